// round 1
// baseline (speedup 1.0000x reference)
#include <cuda_runtime.h>
#include <cstdint>

#define NT      9
#define SEQ     512
#define BATCH   64
#define EMB     1024
#define CHUNKS  8
#define CHUNK_LEN 64

#define L2E 1.4426950408889634f
#define LN2 0.6931471805599453f

// scratch: per-(batch,chunk) 9x9 semiring matrix products
__device__ float g_M[BATCH * CHUNKS * 81];
// tags dtype flag: 1 = int64, 0 = int32
__device__ int   g_tags64;

// ---------------------------------------------------------------------------
// Kernel 1: tag_space = embed @ W^T + b ; emission = log_softmax(tag_space)
// Thread-per-row, K tiled through shared memory. Block = 128 threads = 128 rows.
// Also: block 0 detects tags dtype and zeroes d_out[0].
// ---------------------------------------------------------------------------
__global__ __launch_bounds__(128) void emis_kernel(
    const float* __restrict__ embed,
    const float* __restrict__ W,
    const float* __restrict__ bias,
    const unsigned* __restrict__ tags_words,
    float* __restrict__ out)
{
    __shared__ float sE[128 * 68];   // 128 rows x 64 elems, pad to 68 (conflict-free)
    __shared__ float sW[9 * 64];

    const int tid = threadIdx.x;

    if (blockIdx.x == 0) {
        // tags dtype detection: if int64 (values 0..8), every odd 32-bit word is 0.
        __shared__ int s_any;
        if (tid == 0) s_any = 0;
        __syncthreads();
        int nz = 0;
        for (int q = tid; q < 2048; q += 128)
            nz |= (tags_words[2 * q + 1] != 0u);
        if (nz) atomicOr(&s_any, 1);
        __syncthreads();
        if (tid == 0) {
            g_tags64 = s_any ? 0 : 1;
            out[0] = 0.0f;               // ll accumulator
        }
        __syncthreads();
    }

    const int rowBase = blockIdx.x * 128;

    float acc[NT];
#pragma unroll
    for (int t = 0; t < NT; t++) acc[t] = 0.0f;

    for (int kc = 0; kc < EMB / 64; kc++) {
        // cooperative load of 128x64 embed tile (coalesced float4)
        const float* gsrc = embed + (size_t)rowBase * EMB + kc * 64;
#pragma unroll
        for (int it = 0; it < 16; ++it) {
            int idx = it * 128 + tid;
            int r = idx >> 4, cc = idx & 15;
            float4 v = *(const float4*)(gsrc + (size_t)r * EMB + cc * 4);
            *(float4*)&sE[r * 68 + cc * 4] = v;
        }
        // W chunk: 9 x 64
        for (int idx = tid; idx < 144; idx += 128) {
            int t = idx >> 4, cc = idx & 15;
            *(float4*)&sW[t * 64 + cc * 4] =
                *(const float4*)(W + (size_t)t * EMB + kc * 64 + cc * 4);
        }
        __syncthreads();

        const float* er = &sE[tid * 68];
#pragma unroll 4
        for (int e = 0; e < 64; e += 4) {
            float4 x = *(const float4*)(er + e);
#pragma unroll
            for (int t = 0; t < NT; t++) {
                float4 w = *(const float4*)&sW[t * 64 + e];
                acc[t] = fmaf(x.x, w.x, acc[t]);
                acc[t] = fmaf(x.y, w.y, acc[t]);
                acc[t] = fmaf(x.z, w.z, acc[t]);
                acc[t] = fmaf(x.w, w.w, acc[t]);
            }
        }
        __syncthreads();
    }

#pragma unroll
    for (int t = 0; t < NT; t++) acc[t] += bias[t];

    float mx = acc[0];
#pragma unroll
    for (int t = 1; t < NT; t++) mx = fmaxf(mx, acc[t]);
    float s = 0.0f;
#pragma unroll
    for (int t = 0; t < NT; t++) s += exp2f((acc[t] - mx) * L2E);
    float lse = fmaf(log2f(s), LN2, mx);

    float* o = out + 1 + (size_t)(rowBase + tid) * NT;
#pragma unroll
    for (int t = 0; t < NT; t++) o[t] = acc[t] - lse;
}

// ---------------------------------------------------------------------------
// Kernel 2: chunked forward scan. Associative log-semiring matrix product:
// A_t[i][j] = trans[i][j] + em[t][j] (identity if mask[t]==0).
// block = (chunk c, batch b), 96 threads, thread (i,j) owns M[i][j].
// ---------------------------------------------------------------------------
__global__ __launch_bounds__(96) void crf_chunks(
    const float* __restrict__ outbuf,   // d_out; emission at +1
    const int*   __restrict__ mask,
    const float* __restrict__ trans)
{
    const float* emis = outbuf + 1;
    const int c = blockIdx.x, b = blockIdx.y;
    const int tid = threadIdx.x;

    __shared__ float Ms[2][81];
    __shared__ float str[81];
    if (tid < 81) str[tid] = trans[tid];
    __syncthreads();

    const int i = tid / 9;
    const int j = tid - i * 9;
    float tc[9];                 // trans[k][j]
#pragma unroll
    for (int k = 0; k < 9; k++) tc[k] = str[k * 9 + j];

    const int t0 = 1 + c * CHUNK_LEN;
    const int t1 = min(SEQ, t0 + CHUNK_LEN);
    const float* em_b = emis + (size_t)b * SEQ * NT;
    const int*   mk   = mask + b * SEQ;

    if (tid < 81) Ms[0][tid] = (i == j) ? 0.0f : -1e30f;
    int p = 0;
    bool started = false;
    __syncthreads();

    float emn = (tid < 81) ? em_b[t0 * NT + j] : 0.0f;

    for (int t = t0; t < t1; ++t) {
        float ev = emn;
        if (tid < 81 && t + 1 < t1) emn = em_b[(t + 1) * NT + j];
        const int m = mk[t];
        float outv = 0.0f;
        if (tid < 81) {
            if (m) {
                if (!started) {
                    outv = tc[i] + ev;     // first active step: M = A_t
                } else {
                    const float* Mr = &Ms[p][i * 9];
                    float v0 = Mr[0] + tc[0];
                    float v1 = Mr[1] + tc[1];
                    float v2 = Mr[2] + tc[2];
                    float v3 = Mr[3] + tc[3];
                    float v4 = Mr[4] + tc[4];
                    float v5 = Mr[5] + tc[5];
                    float v6 = Mr[6] + tc[6];
                    float v7 = Mr[7] + tc[7];
                    float v8 = Mr[8] + tc[8];
                    float mx = fmaxf(fmaxf(fmaxf(v0, v1), fmaxf(v2, v3)),
                                     fmaxf(fmaxf(v4, v5), fmaxf(v6, fmaxf(v7, v8))));
                    float s = exp2f((v0 - mx) * L2E);
                    s += exp2f((v1 - mx) * L2E);
                    s += exp2f((v2 - mx) * L2E);
                    s += exp2f((v3 - mx) * L2E);
                    s += exp2f((v4 - mx) * L2E);
                    s += exp2f((v5 - mx) * L2E);
                    s += exp2f((v6 - mx) * L2E);
                    s += exp2f((v7 - mx) * L2E);
                    s += exp2f((v8 - mx) * L2E);
                    outv = fmaf(log2f(s), LN2, mx) + ev;
                }
            } else {
                outv = Ms[p][tid];         // identity step
            }
        }
        if (tid < 81) Ms[p ^ 1][tid] = outv;
        p ^= 1;
        started = started || (m != 0);
        __syncthreads();
    }

    if (tid < 81) g_M[(b * CHUNKS + c) * 81 + tid] = Ms[p][tid];
}

// ---------------------------------------------------------------------------
// Kernel 3: per-batch numerator + chunk-combine + denominator + atomicAdd ll.
// ---------------------------------------------------------------------------
__global__ __launch_bounds__(128) void crf_final(
    float* __restrict__ outbuf,
    const void* __restrict__ tags,
    const int*  __restrict__ mask,
    const float* __restrict__ startT,
    const float* __restrict__ endT,
    const float* __restrict__ trans)
{
    const float* emis = outbuf + 1;
    const int b = blockIdx.x;
    const int tid = threadIdx.x;
    const float* em_b = emis + (size_t)b * SEQ * NT;
    const long long* t64 = (const long long*)tags;
    const int*       t32 = (const int*)tags;
    const int is64 = g_tags64;

    __shared__ float redf[128];
    __shared__ int   redi[128];
    __shared__ float Ms[81];
    __shared__ float s_num;

    // numerator (parallel over s) + mask count
    float acc = 0.0f;
    int   msum = 0;
    for (int s = tid; s < SEQ; s += 128) {
        int m = mask[b * SEQ + s];
        msum += m;
        if (s >= 1) {
            int tp  = is64 ? (int)t64[b * SEQ + s - 1] : t32[b * SEQ + s - 1];
            int tcu = is64 ? (int)t64[b * SEQ + s]     : t32[b * SEQ + s];
            acc += (float)m * (trans[tp * 9 + tcu] + em_b[s * NT + tcu]);
        }
    }
    redf[tid] = acc; redi[tid] = msum;
    __syncthreads();
    for (int o = 64; o > 0; o >>= 1) {
        if (tid < o) { redf[tid] += redf[tid + o]; redi[tid] += redi[tid + o]; }
        __syncthreads();
    }
    if (tid == 0) {
        int tg0  = is64 ? (int)t64[b * SEQ] : t32[b * SEQ];
        int last = redi[0] - 1;
        int tl   = is64 ? (int)t64[b * SEQ + last] : t32[b * SEQ + last];
        s_num = redf[0] + startT[tg0] + em_b[tg0] + endT[tl];
    }
    __syncthreads();

    // combine chunk matrices (warp 0, lanes 0..8 hold the score vector)
    if (tid < 32) {
        const int j = tid;
        float v = (j < 9) ? (startT[j] + em_b[j]) : -1e30f;
        for (int c = 0; c < CHUNKS; c++) {
            const float* Mc = g_M + (b * CHUNKS + c) * 81;
            for (int q = tid; q < 81; q += 32) Ms[q] = Mc[q];
            __syncwarp();
            float vals[9];
#pragma unroll
            for (int i2 = 0; i2 < 9; i2++) {
                float sv = __shfl_sync(0xffffffffu, v, i2);
                vals[i2] = sv + ((j < 9) ? Ms[i2 * 9 + j] : 0.0f);
            }
            float nv = -1e30f;
            if (j < 9) {
                float mx = vals[0];
#pragma unroll
                for (int i2 = 1; i2 < 9; i2++) mx = fmaxf(mx, vals[i2]);
                float s = 0.0f;
#pragma unroll
                for (int i2 = 0; i2 < 9; i2++) s += exp2f((vals[i2] - mx) * L2E);
                nv = fmaf(log2f(s), LN2, mx);
            }
            __syncwarp();
            v = nv;
        }
        // denominator = logsumexp(v + end)
        float x = (j < 9) ? v + endT[j] : -1e30f;
        float mx = x;
#pragma unroll
        for (int o = 16; o > 0; o >>= 1) mx = fmaxf(mx, __shfl_xor_sync(0xffffffffu, mx, o));
        float e = (j < 9) ? exp2f((x - mx) * L2E) : 0.0f;
#pragma unroll
        for (int o = 16; o > 0; o >>= 1) e += __shfl_xor_sync(0xffffffffu, e, o);
        if (tid == 0) {
            float den = fmaf(log2f(e), LN2, mx);
            atomicAdd(outbuf, s_num - den);
        }
    }
}

// ---------------------------------------------------------------------------
extern "C" void kernel_launch(void* const* d_in, const int* in_sizes, int n_in,
                              void* d_out, int out_size)
{
    const float* embed  = (const float*)d_in[0];
    const void*  tags   = d_in[1];
    const int*   mask   = (const int*)d_in[2];
    const float* W      = (const float*)d_in[3];
    const float* bias   = (const float*)d_in[4];
    const float* startT = (const float*)d_in[5];
    const float* endT   = (const float*)d_in[6];
    const float* trans  = (const float*)d_in[7];
    float* out = (float*)d_out;

    emis_kernel<<<(BATCH * SEQ) / 128, 128>>>(embed, W, bias,
                                              (const unsigned*)tags, out);
    dim3 g2(CHUNKS, BATCH);
    crf_chunks<<<g2, 96>>>(out, mask, trans);
    crf_final<<<BATCH, 128>>>(out, tags, mask, startT, endT, trans);
}